// round 17
// baseline (speedup 1.0000x reference)
#include <cuda_runtime.h>
#include <cstdint>

// Problem constants (match reference)
#define N_EVENTS   16
#define N_SAMPLES  32768
#define STEP_SIZE  256
#define BATCH      64

// out[b,j] = sum_e (j >= 256*idx[b,e]) ? x[b,e, j - 256*idx[b,e]] : 0
//
// The reference's scatter-add is inverted into a pure gather: each event's
// segment lands at frame-aligned offset t = 256*idx[b,e], positions >= S
// are discarded, so each output sample is a predicated 16-way sum.
// Race-free, atomic-free; every covered input element is read exactly once
// (event tails beyond S-t are never touched): ~67.6 MB compulsory reads
// + 8.4 MB writes.
//
// FINAL — at the HBM roofline. Floor 10.72 us = ~7.1 TB/s achieved (88% of
// 8 TB/s spec), hit four times by this exact config (R2/R9/R11/R16) across
// 16 controlled experiments spanning work/thread (1x/2x float4), CTA shape
// (128/256t), grid (512-4096 CTAs, persistent single-wave), cache hints
// (__ldcs/__stcs), index path (smem broadcast vs direct), and occupancy
// (45-82%). Identical-code re-runs differ by a full +-0.26us timer quantum,
// so all sound variants are statistical ties at the wall.
//
// Layout: each thread produces 4 consecutive output samples (float4);
// 256 threads/CTA -> 1024 samples/CTA; grid (32 chunks, 64 batches).
// Per event each CTA reads ONE contiguous 4KB region (fully coalesced).
// With blockIdx.x fastest, every 32 consecutive CTAs span the full coverage
// range, so resident waves are naturally load-balanced. Indices loaded
// directly per-thread (uniform within warp -> L1 broadcast, no smem, no
// barrier). regs=32, occupancy ~75-80%.
#define THREADS    256
#define SAMPLES_PER_BLOCK (THREADS * 4)

__global__ __launch_bounds__(THREADS)
void render_gather_kernel(const float* __restrict__ x,
                          const int* __restrict__ indices,
                          float* __restrict__ out) {
    const int b = blockIdx.y;
    const int j = (blockIdx.x * THREADS + threadIdx.x) * 4;  // output sample base

    const int* idx_b = indices + b * N_EVENTS;
    const float* xb = x + (size_t)b * N_EVENTS * N_SAMPLES;

    float4 acc = make_float4(0.f, 0.f, 0.f, 0.f);
    #pragma unroll
    for (int e = 0; e < N_EVENTS; e++) {
        const int t = __ldg(idx_b + e) * STEP_SIZE;   // uniform across warp
        const int k = j - t;
        // t multiple of 256, j multiple of 4 -> k multiple of 4 (16B aligned).
        // k < N_SAMPLES always holds since j < N_SAMPLES and t >= 0.
        if (k >= 0) {
            const float4 v = *reinterpret_cast<const float4*>(
                xb + (size_t)e * N_SAMPLES + k);
            acc.x += v.x; acc.y += v.y; acc.z += v.z; acc.w += v.w;
        }
    }

    *reinterpret_cast<float4*>(out + (size_t)b * N_SAMPLES + j) = acc;
}

extern "C" void kernel_launch(void* const* d_in, const int* in_sizes, int n_in,
                              void* d_out, int out_size) {
    const float* x = (const float*)d_in[0];          // (64, 16, 32768) f32
    const int* indices = (const int*)d_in[1];        // (64, 16) int32
    float* out = (float*)d_out;                      // (64, 1, 32768) f32

    dim3 grid(N_SAMPLES / SAMPLES_PER_BLOCK, BATCH); // (32, 64) = 2048 CTAs
    render_gather_kernel<<<grid, THREADS>>>(x, indices, out);
}